// round 1
// baseline (speedup 1.0000x reference)
#include <cuda_runtime.h>
#include <cstdint>

#define B_      32
#define T_      4096
#define H_      512
#define GRID_   128
#define THREADS_ 256

// Persistent device state (re-initialized every launch by init_kernel).
__device__ float    g_h[2][H_ * B_];   // double-buffered h state, layout [k][b]
__device__ float    g_xT[T_ * B_];     // x transposed to [t][b]
__device__ unsigned g_count;
__device__ unsigned g_gen;

__device__ __forceinline__ float ldcg_f(const float* p) {
    float v; asm volatile("ld.global.cg.f32 %0, [%1];" : "=f"(v) : "l"(p)); return v;
}
__device__ __forceinline__ void stcg_f(float* p, float v) {
    asm volatile("st.global.cg.f32 [%0], %1;" :: "l"(p), "f"(v));
}
__device__ __forceinline__ unsigned ld_acq(const unsigned* p) {
    unsigned v; asm volatile("ld.global.acquire.gpu.u32 %0, [%1];" : "=r"(v) : "l"(p)); return v;
}
__device__ __forceinline__ void st_rel(unsigned* p, unsigned v) {
    asm volatile("st.global.release.gpu.u32 [%0], %1;" :: "l"(p), "r"(v));
}

__global__ void init_kernel(const float* __restrict__ x) {
    int idx = blockIdx.x * blockDim.x + threadIdx.x;
    int stride = gridDim.x * blockDim.x;
    if (idx < H_ * B_) g_h[0][idx] = 0.0f;
    for (int i = idx; i < T_ * B_; i += stride) {
        int t = i / B_;
        int b = i - t * B_;
        g_xT[i] = x[(size_t)b * T_ + t];
    }
    if (idx == 0) { g_count = 0u; g_gen = 0u; }
}

__global__ void __launch_bounds__(THREADS_, 1) lstm_kernel(
    const float* __restrict__ Wih,
    const float* __restrict__ Whh,
    const float* __restrict__ bih,
    const float* __restrict__ bhh,
    float* __restrict__ out,
    int write_final)
{
    // 32 KB: W slice, k-major:  sW[k][r], r = q*4 + u_local  (q = gate i/f/g/o)
    __shared__ float4 sWv[H_ * 4];
    // 16 KB: k-split partial sums: sPart[warp][r][b]
    __shared__ float  sPart[8][16][32];

    const int tid  = threadIdx.x;
    const int warp = tid >> 5;
    const int lane = tid & 31;
    const int u0   = blockIdx.x * 4;

    // Load W_hh slice into smem (once).  sW[k*16 + r] = Whh[(q*512 + u0 + l)*512 + k]
    float* sWf = (float*)sWv;
    for (int i = tid; i < 16 * H_; i += THREADS_) {
        int r = i & 15;
        int k = i >> 4;
        int q = r >> 2;
        int l = r & 3;
        sWf[k * 16 + r] = Whh[(size_t)(q * H_ + u0 + l) * H_ + k];
    }

    // Pointwise threads (tid < 128): per-thread constants and persistent state.
    const int u_l = tid >> 5;   // 0..3 when tid<128
    const int b   = tid & 31;
    float bias[4], wih[4];
    float h_loc = 0.0f, c_loc = 0.0f;
    if (tid < 128) {
#pragma unroll
        for (int q = 0; q < 4; q++) {
            int j = q * H_ + u0 + u_l;
            bias[q] = bih[j] + bhh[j];
            wih[q]  = Wih[j];
        }
    }
    __syncthreads();

    const int kbase = warp * 64;

    for (int t = 0; t < T_; t++) {
        const int p = t & 1;

        // ---- Phase A: GEMM partials. Warp w covers k in [w*64, w*64+64). ----
        const float* hsrc = &g_h[p][kbase * B_ + lane];
        float hreg[64];
#pragma unroll
        for (int kk = 0; kk < 64; kk++) hreg[kk] = ldcg_f(hsrc + kk * B_);

        float acc[16];
#pragma unroll
        for (int r = 0; r < 16; r++) acc[r] = 0.0f;

#pragma unroll
        for (int kk = 0; kk < 64; kk++) {
            const float4* wp = &sWv[(kbase + kk) * 4];
            float4 w0 = wp[0];
            float4 w1 = wp[1];
            float4 w2 = wp[2];
            float4 w3 = wp[3];
            float  h  = hreg[kk];
            acc[0]  = fmaf(w0.x, h, acc[0]);
            acc[1]  = fmaf(w0.y, h, acc[1]);
            acc[2]  = fmaf(w0.z, h, acc[2]);
            acc[3]  = fmaf(w0.w, h, acc[3]);
            acc[4]  = fmaf(w1.x, h, acc[4]);
            acc[5]  = fmaf(w1.y, h, acc[5]);
            acc[6]  = fmaf(w1.z, h, acc[6]);
            acc[7]  = fmaf(w1.w, h, acc[7]);
            acc[8]  = fmaf(w2.x, h, acc[8]);
            acc[9]  = fmaf(w2.y, h, acc[9]);
            acc[10] = fmaf(w2.z, h, acc[10]);
            acc[11] = fmaf(w2.w, h, acc[11]);
            acc[12] = fmaf(w3.x, h, acc[12]);
            acc[13] = fmaf(w3.y, h, acc[13]);
            acc[14] = fmaf(w3.z, h, acc[14]);
            acc[15] = fmaf(w3.w, h, acc[15]);
        }
#pragma unroll
        for (int r = 0; r < 16; r++) sPart[warp][r][lane] = acc[r];
        __syncthreads();

        // ---- Phase B: reduce + pointwise + state update (128 threads). ----
        if (tid < 128) {
            float g4[4];
#pragma unroll
            for (int q = 0; q < 4; q++) {
                float s = 0.0f;
#pragma unroll
                for (int w = 0; w < 8; w++) s += sPart[w][q * 4 + u_l][b];
                g4[q] = fmaf(g_xT[t * B_ + b], wih[q], bias[q]) + s;
            }
            float is = 1.0f / (1.0f + __expf(-g4[0]));
            float fs = 1.0f / (1.0f + __expf(-g4[1]));
            float gs = tanhf(g4[2]);
            float os = 1.0f / (1.0f + __expf(-g4[3]));

            float cn = fs * c_loc + is * gs;
            float hn = os * tanhf(cn);

            h_loc = 0.5f * (h_loc + hn);
            c_loc = 0.5f * (c_loc + cn);

            stcg_f(&g_h[p ^ 1][(u0 + u_l) * B_ + b], h_loc);
            out[((size_t)b * T_ + t) * H_ + u0 + u_l] = h_loc;

            if (write_final && t == T_ - 1) {
                float* o2 = out + (size_t)B_ * T_ * H_;
                o2[b * (2 * H_) + u0 + u_l]      = h_loc;
                o2[b * (2 * H_) + H_ + u0 + u_l] = c_loc;
            }
        }

        // ---- Grid barrier (all 128 CTAs resident; spin-safe). ----
        __threadfence();
        __syncthreads();
        if (tid == 0) {
            unsigned arrived = atomicAdd(&g_count, 1u) + 1u;
            unsigned tgt = (unsigned)(t + 1) * (unsigned)GRID_;
            if (arrived == tgt) {
                st_rel(&g_gen, (unsigned)(t + 1));
            } else {
                while (ld_acq(&g_gen) < (unsigned)(t + 1)) { }
            }
        }
        __syncthreads();
    }
}

extern "C" void kernel_launch(void* const* d_in, const int* in_sizes, int n_in,
                              void* d_out, int out_size)
{
    const float* x   = (const float*)d_in[0];
    const float* Wih = (const float*)d_in[1];
    const float* Whh = (const float*)d_in[2];
    const float* bih = (const float*)d_in[3];
    const float* bhh = (const float*)d_in[4];
    float* out = (float*)d_out;

    int need = B_ * T_ * H_ + B_ * 2 * H_;
    int write_final = (out_size >= need) ? 1 : 0;

    init_kernel<<<256, THREADS_>>>(x);
    lstm_kernel<<<GRID_, THREADS_>>>(Wih, Whh, bih, bhh, out, write_final);
}

// round 2
// speedup vs baseline: 1.0684x; 1.0684x over previous
#include <cuda_runtime.h>
#include <cstdint>

#define B_       32
#define T_       4096
#define H_       512
#define GRID_    128
#define THREADS_ 512
#define NW_      16    // warps per CTA
#define KW_      32    // k-chunk per warp

// Persistent device state (re-initialized every launch by init_kernel).
__device__ float    g_h[2][H_ * B_];   // double-buffered h state, layout [k][b]
__device__ float    g_xT[T_ * B_];     // x transposed to [t][b]
__device__ unsigned g_count;
__device__ unsigned g_gen;

__device__ __forceinline__ float ldcg_f(const float* p) {
    float v; asm volatile("ld.global.cg.f32 %0, [%1];" : "=f"(v) : "l"(p)); return v;
}
__device__ __forceinline__ void stcg_f(float* p, float v) {
    asm volatile("st.global.cg.f32 [%0], %1;" :: "l"(p), "f"(v));
}
__device__ __forceinline__ unsigned ld_acq(const unsigned* p) {
    unsigned v; asm volatile("ld.global.acquire.gpu.u32 %0, [%1];" : "=r"(v) : "l"(p)); return v;
}
__device__ __forceinline__ void st_rel(unsigned* p, unsigned v) {
    asm volatile("st.global.release.gpu.u32 [%0], %1;" :: "l"(p), "r"(v));
}
__device__ __forceinline__ unsigned atom_add_acqrel(unsigned* p, unsigned v) {
    unsigned old;
    asm volatile("atom.acq_rel.gpu.global.add.u32 %0, [%1], %2;"
                 : "=r"(old) : "l"(p), "r"(v));
    return old;
}
// packed fp32x2 fma: a.{lo,hi} += w.{lo,hi} * h.{lo,hi}
__device__ __forceinline__ void ffma2(unsigned long long& a,
                                      unsigned long long w,
                                      unsigned long long h) {
    asm("fma.rn.f32x2 %0, %1, %2, %0;" : "+l"(a) : "l"(w), "l"(h));
}

__global__ void init_kernel(const float* __restrict__ x) {
    int idx = blockIdx.x * blockDim.x + threadIdx.x;
    int stride = gridDim.x * blockDim.x;
    if (idx < H_ * B_) g_h[0][idx] = 0.0f;
    for (int i = idx; i < T_ * B_; i += stride) {
        int t = i / B_;
        int b = i - t * B_;
        g_xT[i] = x[(size_t)b * T_ + t];
    }
    if (idx == 0) { g_count = 0u; g_gen = 0u; }
}

__global__ void __launch_bounds__(THREADS_, 1) lstm_kernel(
    const float* __restrict__ Wih,
    const float* __restrict__ Whh,
    const float* __restrict__ bih,
    const float* __restrict__ bhh,
    float* __restrict__ out,
    int write_final)
{
    extern __shared__ float smem[];
    float* sW    = smem;               // [k][16 r]  : 16*512 floats (32 KB)
    float* sPart = smem + 16 * H_;     // [16 w][16 r][32 b] : 8192 floats (32 KB)
    float* sOut  = smem + 32 * H_;     // [32 b][4 u] : 128 floats

    const int tid  = threadIdx.x;
    const int warp = tid >> 5;
    const int lane = tid & 31;
    const int u0   = blockIdx.x * 4;

    // Load W_hh slice (16 rows x 512 k) into smem, k-major pairs.
    for (int i = tid; i < 16 * H_; i += THREADS_) {
        int r = i & 15;
        int k = i >> 4;
        int q = r >> 2;
        int l = r & 3;
        sW[k * 16 + r] = Whh[(size_t)(q * H_ + u0 + l) * H_ + k];
    }

    // Pointwise threads (tid < 128): constants + persistent register state.
    const int u_l = tid >> 5;   // 0..3 when tid<128
    const int b   = tid & 31;
    float bias[4], wih[4];
    float h_loc = 0.0f, c_loc = 0.0f;
    if (tid < 128) {
#pragma unroll
        for (int q = 0; q < 4; q++) {
            int j = q * H_ + u0 + u_l;
            bias[q] = bih[j] + bhh[j];
            wih[q]  = Wih[j];
        }
    }
    __syncthreads();

    const int kbase = warp * KW_;

    for (int t = 0; t < T_; t++) {
        const int p = t & 1;

        float xv = 0.0f;
        if (tid < 128) xv = g_xT[t * B_ + b];   // prefetch x early

        // ---- Phase A: GEMM partials (warp covers k in [kbase, kbase+32)) ----
        const float* hsrc = &g_h[p][kbase * B_ + lane];
        float hreg[KW_];
#pragma unroll
        for (int kk = 0; kk < KW_; kk++) hreg[kk] = ldcg_f(hsrc + kk * B_);

        unsigned long long acc[8];
#pragma unroll
        for (int r = 0; r < 8; r++) acc[r] = 0ULL;

#pragma unroll
        for (int kk = 0; kk < KW_; kk++) {
            unsigned long long hh;
            asm("mov.b64 %0, {%1, %1};" : "=l"(hh) : "f"(hreg[kk]));
            const ulonglong2* wp = (const ulonglong2*)(sW + (kbase + kk) * 16);
            ulonglong2 a0 = wp[0];
            ulonglong2 a1 = wp[1];
            ulonglong2 a2 = wp[2];
            ulonglong2 a3 = wp[3];
            ffma2(acc[0], a0.x, hh); ffma2(acc[1], a0.y, hh);
            ffma2(acc[2], a1.x, hh); ffma2(acc[3], a1.y, hh);
            ffma2(acc[4], a2.x, hh); ffma2(acc[5], a2.y, hh);
            ffma2(acc[6], a3.x, hh); ffma2(acc[7], a3.y, hh);
        }
#pragma unroll
        for (int r = 0; r < 8; r++) {
            float lo, hi;
            asm("mov.b64 {%0, %1}, %2;" : "=f"(lo), "=f"(hi) : "l"(acc[r]));
            sPart[(warp * 16 + 2 * r)     * 32 + lane] = lo;
            sPart[(warp * 16 + 2 * r + 1) * 32 + lane] = hi;
        }
        __syncthreads();

        // ---- Phase B: reduce + pointwise + state update (128 threads) ----
        if (tid < 128) {
            float g4[4];
#pragma unroll
            for (int q = 0; q < 4; q++) {
                int r = q * 4 + u_l;
                float s0 = 0.f, s1 = 0.f, s2 = 0.f, s3 = 0.f;
#pragma unroll
                for (int w = 0; w < NW_; w += 4) {
                    s0 += sPart[((w + 0) * 16 + r) * 32 + b];
                    s1 += sPart[((w + 1) * 16 + r) * 32 + b];
                    s2 += sPart[((w + 2) * 16 + r) * 32 + b];
                    s3 += sPart[((w + 3) * 16 + r) * 32 + b];
                }
                g4[q] = fmaf(xv, wih[q], bias[q]) + ((s0 + s1) + (s2 + s3));
            }
            float is = 1.0f / (1.0f + __expf(-g4[0]));
            float fs = 1.0f / (1.0f + __expf(-g4[1]));
            float gs = tanhf(g4[2]);
            float os = 1.0f / (1.0f + __expf(-g4[3]));

            float cn = fs * c_loc + is * gs;
            float hn = os * tanhf(cn);

            h_loc = 0.5f * (h_loc + hn);
            c_loc = 0.5f * (c_loc + cn);

            stcg_f(&g_h[p ^ 1][(u0 + u_l) * B_ + b], h_loc);
            sOut[b * 4 + u_l] = h_loc;

            if (write_final && t == T_ - 1) {
                float* o2 = out + (size_t)B_ * T_ * H_;
                o2[b * (2 * H_) + u0 + u_l]      = h_loc;
                o2[b * (2 * H_) + H_ + u0 + u_l] = c_loc;
            }
        }
        __syncthreads();

        // coalesced streaming output write: one float4 per batch
        if (warp == 0) {
            const float4 v = *(const float4*)(sOut + lane * 4);
            float* dst = out + ((size_t)lane * T_ + t) * H_ + u0;
            asm volatile("st.global.cs.v4.f32 [%0], {%1,%2,%3,%4};"
                         :: "l"(dst), "f"(v.x), "f"(v.y), "f"(v.z), "f"(v.w));
        }

        // ---- Grid barrier (release/acquire, no threadfence) ----
        if (tid == 0) {
            unsigned old = atom_add_acqrel(&g_count, 1u);
            unsigned tgt = (unsigned)(t + 1) * (unsigned)GRID_;
            if (old + 1u == tgt) {
                st_rel(&g_gen, (unsigned)(t + 1));
            } else {
                while (ld_acq(&g_gen) < (unsigned)(t + 1)) { }
            }
        }
        __syncthreads();
    }
}

extern "C" void kernel_launch(void* const* d_in, const int* in_sizes, int n_in,
                              void* d_out, int out_size)
{
    const float* x   = (const float*)d_in[0];
    const float* Wih = (const float*)d_in[1];
    const float* Whh = (const float*)d_in[2];
    const float* bih = (const float*)d_in[3];
    const float* bhh = (const float*)d_in[4];
    float* out = (float*)d_out;

    int need = B_ * T_ * H_ + B_ * 2 * H_;
    int write_final = (out_size >= need) ? 1 : 0;

    static int smem_set = 0;
    const int smem_bytes = (16 * H_ + 16 * H_ + 128) * sizeof(float);
    if (!smem_set) {
        cudaFuncSetAttribute(lstm_kernel,
                             cudaFuncAttributeMaxDynamicSharedMemorySize,
                             smem_bytes);
        smem_set = 1;
    }

    init_kernel<<<256, 256>>>(x);
    lstm_kernel<<<GRID_, THREADS_, smem_bytes>>>(Wih, Whh, bih, bhh, out, write_final);
}

// round 3
// speedup vs baseline: 1.0725x; 1.0038x over previous
#include <cuda_runtime.h>
#include <cstdint>

#define B_       32
#define T_       4096
#define H_       512
#define GRID_    128
#define THREADS_ 512
#define NW_      16    // warps per CTA
#define KW_      32    // k-chunk per warp

// Persistent device state (re-initialized every launch by init_kernel).
__device__ float    g_h[2][H_ * B_];   // double-buffered h state, layout [k][b]
__device__ float    g_xT[T_ * B_];     // x transposed to [t][b]
__device__ unsigned g_count;
__device__ unsigned g_gen;

__device__ __forceinline__ float ldcg_f(const float* p) {
    float v; asm volatile("ld.global.cg.f32 %0, [%1];" : "=f"(v) : "l"(p)); return v;
}
__device__ __forceinline__ void stcg_f(float* p, float v) {
    asm volatile("st.global.cg.f32 [%0], %1;" :: "l"(p), "f"(v));
}
__device__ __forceinline__ unsigned ld_acq(const unsigned* p) {
    unsigned v; asm volatile("ld.global.acquire.gpu.u32 %0, [%1];" : "=r"(v) : "l"(p)); return v;
}
__device__ __forceinline__ void st_rel(unsigned* p, unsigned v) {
    asm volatile("st.global.release.gpu.u32 [%0], %1;" :: "l"(p), "r"(v));
}
__device__ __forceinline__ unsigned atom_add_acqrel(unsigned* p, unsigned v) {
    unsigned old;
    asm volatile("atom.acq_rel.gpu.global.add.u32 %0, [%1], %2;"
                 : "=r"(old) : "l"(p), "r"(v));
    return old;
}
// packed fp32x2 fma: a.{lo,hi} += w.{lo,hi} * h.{lo,hi}
__device__ __forceinline__ void ffma2(unsigned long long& a,
                                      unsigned long long w,
                                      unsigned long long h) {
    asm("fma.rn.f32x2 %0, %1, %2, %0;" : "+l"(a) : "l"(w), "l"(h));
}

__global__ void init_kernel(const float* __restrict__ x) {
    int idx = blockIdx.x * blockDim.x + threadIdx.x;
    int stride = gridDim.x * blockDim.x;
    if (idx < H_ * B_) g_h[0][idx] = 0.0f;
    for (int i = idx; i < T_ * B_; i += stride) {
        int t = i / B_;
        int b = i - t * B_;
        g_xT[i] = x[(size_t)b * T_ + t];
    }
    if (idx == 0) { g_count = 0u; g_gen = 0u; }
}

__global__ void __launch_bounds__(THREADS_, 1) lstm_kernel(
    const float* __restrict__ Wih,
    const float* __restrict__ Whh,
    const float* __restrict__ bih,
    const float* __restrict__ bhh,
    float* __restrict__ out,
    int write_final)
{
    extern __shared__ float smem[];
    float* sW    = smem;               // [k][16 r]  : 16*512 floats (32 KB)
    float* sPart = smem + 16 * H_;     // [16 w][16 r][32 b] : 8192 floats (32 KB)
    float* sOut  = smem + 32 * H_;     // [32 b][4 u] : 128 floats

    const int tid  = threadIdx.x;
    const int warp = tid >> 5;
    const int lane = tid & 31;
    const int u0   = blockIdx.x * 4;

    // Load W_hh slice (16 rows x 512 k) into smem, k-major pairs.
    for (int i = tid; i < 16 * H_; i += THREADS_) {
        int r = i & 15;
        int k = i >> 4;
        int q = r >> 2;
        int l = r & 3;
        sW[k * 16 + r] = Whh[(size_t)(q * H_ + u0 + l) * H_ + k];
    }

    // Pointwise threads (tid < 128): constants + persistent register state.
    const int u_l = tid >> 5;   // 0..3 when tid<128
    const int b   = tid & 31;
    float bias[4], wih[4];
    float h_loc = 0.0f, c_loc = 0.0f;
    if (tid < 128) {
#pragma unroll
        for (int q = 0; q < 4; q++) {
            int j = q * H_ + u0 + u_l;
            bias[q] = bih[j] + bhh[j];
            wih[q]  = Wih[j];
        }
    }
    __syncthreads();

    const int kbase = warp * KW_;

    for (int t = 0; t < T_; t++) {
        const int p = t & 1;

        float xv = 0.0f;
        if (tid < 128) xv = g_xT[t * B_ + b];   // prefetch x early

        // ---- Phase A: GEMM partials (warp covers k in [kbase, kbase+32)) ----
        const float* hsrc = &g_h[p][kbase * B_ + lane];
        float hreg[KW_];
#pragma unroll
        for (int kk = 0; kk < KW_; kk++) hreg[kk] = ldcg_f(hsrc + kk * B_);

        unsigned long long acc[8];
#pragma unroll
        for (int r = 0; r < 8; r++) acc[r] = 0ULL;

#pragma unroll
        for (int kk = 0; kk < KW_; kk++) {
            unsigned long long hh;
            asm("mov.b64 %0, {%1, %1};" : "=l"(hh) : "f"(hreg[kk]));
            const ulonglong2* wp = (const ulonglong2*)(sW + (kbase + kk) * 16);
            ulonglong2 a0 = wp[0];
            ulonglong2 a1 = wp[1];
            ulonglong2 a2 = wp[2];
            ulonglong2 a3 = wp[3];
            ffma2(acc[0], a0.x, hh); ffma2(acc[1], a0.y, hh);
            ffma2(acc[2], a1.x, hh); ffma2(acc[3], a1.y, hh);
            ffma2(acc[4], a2.x, hh); ffma2(acc[5], a2.y, hh);
            ffma2(acc[6], a3.x, hh); ffma2(acc[7], a3.y, hh);
        }
#pragma unroll
        for (int r = 0; r < 8; r++) {
            float lo, hi;
            asm("mov.b64 {%0, %1}, %2;" : "=f"(lo), "=f"(hi) : "l"(acc[r]));
            sPart[(warp * 16 + 2 * r)     * 32 + lane] = lo;
            sPart[(warp * 16 + 2 * r + 1) * 32 + lane] = hi;
        }
        __syncthreads();

        // ---- Phase B: reduce + pointwise + state update (128 threads) ----
        if (tid < 128) {
            float g4[4];
#pragma unroll
            for (int q = 0; q < 4; q++) {
                int r = q * 4 + u_l;
                float s0 = 0.f, s1 = 0.f, s2 = 0.f, s3 = 0.f;
#pragma unroll
                for (int w = 0; w < NW_; w += 4) {
                    s0 += sPart[((w + 0) * 16 + r) * 32 + b];
                    s1 += sPart[((w + 1) * 16 + r) * 32 + b];
                    s2 += sPart[((w + 2) * 16 + r) * 32 + b];
                    s3 += sPart[((w + 3) * 16 + r) * 32 + b];
                }
                g4[q] = fmaf(xv, wih[q], bias[q]) + ((s0 + s1) + (s2 + s3));
            }
            float is = 1.0f / (1.0f + __expf(-g4[0]));
            float fs = 1.0f / (1.0f + __expf(-g4[1]));
            float gs = tanhf(g4[2]);
            float os = 1.0f / (1.0f + __expf(-g4[3]));

            float cn = fs * c_loc + is * gs;
            float hn = os * tanhf(cn);

            h_loc = 0.5f * (h_loc + hn);
            c_loc = 0.5f * (c_loc + cn);

            stcg_f(&g_h[p ^ 1][(u0 + u_l) * B_ + b], h_loc);
            sOut[b * 4 + u_l] = h_loc;

            if (write_final && t == T_ - 1) {
                float* o2 = out + (size_t)B_ * T_ * H_;
                o2[b * (2 * H_) + u0 + u_l]      = h_loc;
                o2[b * (2 * H_) + H_ + u0 + u_l] = c_loc;
            }
        }
        __syncthreads();

        // coalesced streaming output write: one float4 per batch
        if (warp == 0) {
            const float4 v = *(const float4*)(sOut + lane * 4);
            float* dst = out + ((size_t)lane * T_ + t) * H_ + u0;
            asm volatile("st.global.cs.v4.f32 [%0], {%1,%2,%3,%4};"
                         :: "l"(dst), "f"(v.x), "f"(v.y), "f"(v.z), "f"(v.w));
        }

        // ---- Grid barrier (release/acquire, no threadfence) ----
        if (tid == 0) {
            unsigned old = atom_add_acqrel(&g_count, 1u);
            unsigned tgt = (unsigned)(t + 1) * (unsigned)GRID_;
            if (old + 1u == tgt) {
                st_rel(&g_gen, (unsigned)(t + 1));
            } else {
                while (ld_acq(&g_gen) < (unsigned)(t + 1)) { }
            }
        }
        __syncthreads();
    }
}

extern "C" void kernel_launch(void* const* d_in, const int* in_sizes, int n_in,
                              void* d_out, int out_size)
{
    const float* x   = (const float*)d_in[0];
    const float* Wih = (const float*)d_in[1];
    const float* Whh = (const float*)d_in[2];
    const float* bih = (const float*)d_in[3];
    const float* bhh = (const float*)d_in[4];
    float* out = (float*)d_out;

    int need = B_ * T_ * H_ + B_ * 2 * H_;
    int write_final = (out_size >= need) ? 1 : 0;

    static int smem_set = 0;
    const int smem_bytes = (16 * H_ + 16 * H_ + 128) * sizeof(float);
    if (!smem_set) {
        cudaFuncSetAttribute(lstm_kernel,
                             cudaFuncAttributeMaxDynamicSharedMemorySize,
                             smem_bytes);
        smem_set = 1;
    }

    init_kernel<<<256, 256>>>(x);
    lstm_kernel<<<GRID_, THREADS_, smem_bytes>>>(Wih, Whh, bih, bhh, out, write_final);
}

// round 4
// speedup vs baseline: 1.0732x; 1.0006x over previous
#include <cuda_runtime.h>
#include <cstdint>

#define B_       32
#define T_       4096
#define H_       512
#define GRID_    128
#define THREADS_ 512
#define NW_      16    // warps per CTA
#define KW_      32    // k-chunk per warp

// Persistent device state (re-initialized every launch by init_kernel).
__device__ float    g_h[2][H_ * B_];   // double-buffered h state, layout [k][b]
__device__ float    g_xT[T_ * B_];     // x transposed to [t][b]
__device__ unsigned g_count;
__device__ unsigned g_gen;

__device__ __forceinline__ float ldcg_f(const float* p) {
    float v; asm volatile("ld.global.cg.f32 %0, [%1];" : "=f"(v) : "l"(p)); return v;
}
__device__ __forceinline__ void stcg_f(float* p, float v) {
    asm volatile("st.global.cg.f32 [%0], %1;" :: "l"(p), "f"(v));
}
__device__ __forceinline__ unsigned ld_acq(const unsigned* p) {
    unsigned v; asm volatile("ld.global.acquire.gpu.u32 %0, [%1];" : "=r"(v) : "l"(p)); return v;
}
__device__ __forceinline__ void st_rel(unsigned* p, unsigned v) {
    asm volatile("st.global.release.gpu.u32 [%0], %1;" :: "l"(p), "r"(v));
}
__device__ __forceinline__ unsigned atom_add_acqrel(unsigned* p, unsigned v) {
    unsigned old;
    asm volatile("atom.acq_rel.gpu.global.add.u32 %0, [%1], %2;"
                 : "=r"(old) : "l"(p), "r"(v));
    return old;
}
// packed fp32x2 fma: a.{lo,hi} += w.{lo,hi} * h.{lo,hi}
__device__ __forceinline__ void ffma2(unsigned long long& a,
                                      unsigned long long w,
                                      unsigned long long h) {
    asm("fma.rn.f32x2 %0, %1, %2, %0;" : "+l"(a) : "l"(w), "l"(h));
}

__global__ void init_kernel(const float* __restrict__ x) {
    int idx = blockIdx.x * blockDim.x + threadIdx.x;
    int stride = gridDim.x * blockDim.x;
    if (idx < H_ * B_) g_h[0][idx] = 0.0f;
    for (int i = idx; i < T_ * B_; i += stride) {
        int t = i / B_;
        int b = i - t * B_;
        g_xT[i] = x[(size_t)b * T_ + t];
    }
    if (idx == 0) { g_count = 0u; g_gen = 0u; }
}

__global__ void __launch_bounds__(THREADS_, 1) lstm_kernel(
    const float* __restrict__ Wih,
    const float* __restrict__ Whh,
    const float* __restrict__ bih,
    const float* __restrict__ bhh,
    float* __restrict__ out,
    int write_final)
{
    extern __shared__ float smem[];
    float* sW    = smem;               // [k][16 r]  : 16*512 floats (32 KB)
    float* sPart = smem + 16 * H_;     // [16 w][16 r][32 b] : 8192 floats (32 KB)
    float* sOut  = smem + 32 * H_;     // [32 b][4 u] : 128 floats

    const int tid  = threadIdx.x;
    const int warp = tid >> 5;
    const int lane = tid & 31;
    const int u0   = blockIdx.x * 4;

    // Load W_hh slice (16 rows x 512 k) into smem, k-major pairs.
    for (int i = tid; i < 16 * H_; i += THREADS_) {
        int r = i & 15;
        int k = i >> 4;
        int q = r >> 2;
        int l = r & 3;
        sW[k * 16 + r] = Whh[(size_t)(q * H_ + u0 + l) * H_ + k];
    }

    // Pointwise threads (tid < 128): constants + persistent register state.
    const int u_l = tid >> 5;   // 0..3 when tid<128
    const int b   = tid & 31;
    float bias[4], wih[4];
    float h_loc = 0.0f, c_loc = 0.0f;
    if (tid < 128) {
#pragma unroll
        for (int q = 0; q < 4; q++) {
            int j = q * H_ + u0 + u_l;
            bias[q] = bih[j] + bhh[j];
            wih[q]  = Wih[j];
        }
    }
    __syncthreads();

    const int kbase = warp * KW_;

    for (int t = 0; t < T_; t++) {
        const int p = t & 1;

        float xv = 0.0f;
        if (tid < 128) xv = g_xT[t * B_ + b];   // prefetch x early

        // ---- Phase A: GEMM partials (warp covers k in [kbase, kbase+32)) ----
        const float* hsrc = &g_h[p][kbase * B_ + lane];
        float hreg[KW_];
#pragma unroll
        for (int kk = 0; kk < KW_; kk++) hreg[kk] = ldcg_f(hsrc + kk * B_);

        unsigned long long acc[8];
#pragma unroll
        for (int r = 0; r < 8; r++) acc[r] = 0ULL;

#pragma unroll
        for (int kk = 0; kk < KW_; kk++) {
            unsigned long long hh;
            asm("mov.b64 %0, {%1, %1};" : "=l"(hh) : "f"(hreg[kk]));
            const ulonglong2* wp = (const ulonglong2*)(sW + (kbase + kk) * 16);
            ulonglong2 a0 = wp[0];
            ulonglong2 a1 = wp[1];
            ulonglong2 a2 = wp[2];
            ulonglong2 a3 = wp[3];
            ffma2(acc[0], a0.x, hh); ffma2(acc[1], a0.y, hh);
            ffma2(acc[2], a1.x, hh); ffma2(acc[3], a1.y, hh);
            ffma2(acc[4], a2.x, hh); ffma2(acc[5], a2.y, hh);
            ffma2(acc[6], a3.x, hh); ffma2(acc[7], a3.y, hh);
        }
#pragma unroll
        for (int r = 0; r < 8; r++) {
            float lo, hi;
            asm("mov.b64 {%0, %1}, %2;" : "=f"(lo), "=f"(hi) : "l"(acc[r]));
            sPart[(warp * 16 + 2 * r)     * 32 + lane] = lo;
            sPart[(warp * 16 + 2 * r + 1) * 32 + lane] = hi;
        }
        __syncthreads();

        // ---- Phase B: reduce + pointwise + state update (128 threads) ----
        if (tid < 128) {
            float g4[4];
#pragma unroll
            for (int q = 0; q < 4; q++) {
                int r = q * 4 + u_l;
                float s0 = 0.f, s1 = 0.f, s2 = 0.f, s3 = 0.f;
#pragma unroll
                for (int w = 0; w < NW_; w += 4) {
                    s0 += sPart[((w + 0) * 16 + r) * 32 + b];
                    s1 += sPart[((w + 1) * 16 + r) * 32 + b];
                    s2 += sPart[((w + 2) * 16 + r) * 32 + b];
                    s3 += sPart[((w + 3) * 16 + r) * 32 + b];
                }
                g4[q] = fmaf(xv, wih[q], bias[q]) + ((s0 + s1) + (s2 + s3));
            }
            float is = 1.0f / (1.0f + __expf(-g4[0]));
            float fs = 1.0f / (1.0f + __expf(-g4[1]));
            float gs = tanhf(g4[2]);
            float os = 1.0f / (1.0f + __expf(-g4[3]));

            float cn = fs * c_loc + is * gs;
            float hn = os * tanhf(cn);

            h_loc = 0.5f * (h_loc + hn);
            c_loc = 0.5f * (c_loc + cn);

            stcg_f(&g_h[p ^ 1][(u0 + u_l) * B_ + b], h_loc);
            sOut[b * 4 + u_l] = h_loc;

            if (write_final && t == T_ - 1) {
                float* o2 = out + (size_t)B_ * T_ * H_;
                o2[b * (2 * H_) + u0 + u_l]      = h_loc;
                o2[b * (2 * H_) + H_ + u0 + u_l] = c_loc;
            }
        }
        __syncthreads();

        // coalesced streaming output write: one float4 per batch
        if (warp == 0) {
            const float4 v = *(const float4*)(sOut + lane * 4);
            float* dst = out + ((size_t)lane * T_ + t) * H_ + u0;
            asm volatile("st.global.cs.v4.f32 [%0], {%1,%2,%3,%4};"
                         :: "l"(dst), "f"(v.x), "f"(v.y), "f"(v.z), "f"(v.w));
        }

        // ---- Grid barrier (release/acquire, no threadfence) ----
        if (tid == 0) {
            unsigned old = atom_add_acqrel(&g_count, 1u);
            unsigned tgt = (unsigned)(t + 1) * (unsigned)GRID_;
            if (old + 1u == tgt) {
                st_rel(&g_gen, (unsigned)(t + 1));
            } else {
                while (ld_acq(&g_gen) < (unsigned)(t + 1)) { }
            }
        }
        __syncthreads();
    }
}

extern "C" void kernel_launch(void* const* d_in, const int* in_sizes, int n_in,
                              void* d_out, int out_size)
{
    const float* x   = (const float*)d_in[0];
    const float* Wih = (const float*)d_in[1];
    const float* Whh = (const float*)d_in[2];
    const float* bih = (const float*)d_in[3];
    const float* bhh = (const float*)d_in[4];
    float* out = (float*)d_out;

    int need = B_ * T_ * H_ + B_ * 2 * H_;
    int write_final = (out_size >= need) ? 1 : 0;

    static int smem_set = 0;
    const int smem_bytes = (16 * H_ + 16 * H_ + 128) * sizeof(float);
    if (!smem_set) {
        cudaFuncSetAttribute(lstm_kernel,
                             cudaFuncAttributeMaxDynamicSharedMemorySize,
                             smem_bytes);
        smem_set = 1;
    }

    init_kernel<<<256, 256>>>(x);
    lstm_kernel<<<GRID_, THREADS_, smem_bytes>>>(Wih, Whh, bih, bhh, out, write_final);
}